// round 13
// baseline (speedup 1.0000x reference)
#include <cuda_runtime.h>
#include <cuda_fp16.h>
#include <math.h>
#include <stdint.h>

#define Bn 2
#define Sn 2048
#define Dn 1024
#define Hn 16
#define HDn 64

#define XSZ (Bn * Sn * Dn)
#define WSZ (Dn * Dn)

// Projected tensors, fp16, layout [B,H,S,HD].
__device__ __half g_qh[XSZ];
__device__ __half g_kh[XSZ];
__device__ __half g_vh[XSZ];

// fp16 gemm inputs.
__device__ __half g_xh[3 * XSZ];
__device__ __half g_wh[3 * WSZ];

// Sync state (zero-initialized at load; last CTA re-zeroes at kernel end,
// so every graph replay starts clean).
__device__ int g_wq;         // work counter
__device__ int g_done;       // finished-CTA counter
__device__ int g_kv[32];     // [which-1][b][nblk] completed m-blocks (target 16)
__device__ int g_qd[256];    // [mblk][nblk] Q tile done flags
__device__ int g_xcv[96];    // [which][mblk] X conversion done
__device__ int g_wcv[24];    // [which][nblk] W conversion done

// ---------------------------------------------------------------------------
// Helpers.
// ---------------------------------------------------------------------------
__device__ __forceinline__ uint32_t smem_u32(const void* p) {
    uint32_t a;
    asm("{ .reg .u64 t; cvta.to.shared.u64 t, %1; cvt.u32.u64 %0, t; }"
        : "=r"(a) : "l"(p));
    return a;
}
__device__ __forceinline__ void ldsm_x4(uint32_t& r0, uint32_t& r1,
                                        uint32_t& r2, uint32_t& r3, uint32_t a) {
    asm volatile("ldmatrix.sync.aligned.m8n8.x4.shared.b16 {%0,%1,%2,%3}, [%4];"
                 : "=r"(r0), "=r"(r1), "=r"(r2), "=r"(r3) : "r"(a));
}
__device__ __forceinline__ void ldsm_x4t(uint32_t& r0, uint32_t& r1,
                                         uint32_t& r2, uint32_t& r3, uint32_t a) {
    asm volatile("ldmatrix.sync.aligned.m8n8.x4.trans.shared.b16 {%0,%1,%2,%3}, [%4];"
                 : "=r"(r0), "=r"(r1), "=r"(r2), "=r"(r3) : "r"(a));
}
__device__ __forceinline__ void mma_f16(float* c, const uint32_t* a,
                                        const uint32_t* b) {
    asm volatile(
        "mma.sync.aligned.m16n8k16.row.col.f32.f16.f16.f32 "
        "{%0,%1,%2,%3}, {%4,%5,%6,%7}, {%8,%9}, {%0,%1,%2,%3};"
        : "+f"(c[0]), "+f"(c[1]), "+f"(c[2]), "+f"(c[3])
        : "r"(a[0]), "r"(a[1]), "r"(a[2]), "r"(a[3]), "r"(b[0]), "r"(b[1]));
}
__device__ __forceinline__ void cp16(uint32_t dst, const void* src) {
    asm volatile("cp.async.cg.shared.global [%0], [%1], 16;"
                 :: "r"(dst), "l"(src));
}
#define CP_COMMIT() asm volatile("cp.async.commit_group;" ::: "memory")
#define CP_WAIT0()  asm volatile("cp.async.wait_group 0;" ::: "memory")
__device__ __forceinline__ void stcs2(float* p, float2 v) {
    asm volatile("st.global.cs.v2.f32 [%0], {%1, %2};" :: "l"(p), "f"(v.x), "f"(v.y));
}
__device__ __forceinline__ uint32_t pf2(float lo, float hi) {
    uint32_t r;
    asm("cvt.rn.f16x2.f32 %0, %1, %2;" : "=r"(r) : "f"(hi), "f"(lo));
    return r;
}
__device__ __forceinline__ int ldacq(const int* p) {
    int v;
    asm volatile("ld.acquire.gpu.global.b32 %0, [%1];" : "=r"(v) : "l"(p));
    return v;
}
__device__ __forceinline__ void wait_ge(const int* p, int v) {
    while (ldacq(p) < v) __nanosleep(200);
}

// ---------------------------------------------------------------------------
// Conversion item: one 128-row block of an input tensor, fp32 -> fp16.
// nrows*1024 elements starting at row blk*128.
// ---------------------------------------------------------------------------
__device__ __forceinline__ void do_convert(int t, const float* __restrict__ src,
                                           __half* __restrict__ dst, int blk)
{
    const size_t base4 = (size_t)blk * 32768;   // float4 index of block start
#pragma unroll 4
    for (int i = t; i < 32768; i += 256) {
        float4 x = ((const float4*)src)[base4 + i];
        ((__half2*)dst)[(base4 + i) * 2 + 0] = __floats2half2_rn(x.x, x.y);
        ((__half2*)dst)[(base4 + i) * 2 + 1] = __floats2half2_rn(x.z, x.w);
    }
}

// ---------------------------------------------------------------------------
// GEMM tile (single-term fp16 HMMA), 128x128, K-chunk 64, 2-stage ring.
// ---------------------------------------------------------------------------
#define KC 64
#define LDP 72
#define TILE_B (128 * LDP * 2)     // 18432
#define GSTAGE (2 * TILE_B)        // 36864

__device__ __forceinline__ void do_gemm(char* smem, int t, int which,
                                        int m0, int n0, const float* bias)
{
    const uint32_t uS = smem_u32(smem);
    const int wid = t >> 5;
    const int lane = t & 31;
    const int wr = wid & 3;
    const int wc = wid >> 2;

    const __half* A = g_xh + (size_t)which * XSZ;
    const __half* B = g_wh + (size_t)which * WSZ;
    __half* outp = which == 0 ? g_qh : (which == 1 ? g_kh : g_vh);

    float acc[2][8][4];
#pragma unroll
    for (int i = 0; i < 2; ++i)
#pragma unroll
        for (int j = 0; j < 8; ++j)
#pragma unroll
            for (int e = 0; e < 4; ++e) acc[i][j][e] = 0.f;

    const uint32_t aOff = (uint32_t)(((wr * 32 + (lane & 15)) * LDP + (lane >> 4) * 8) * 2);

    auto prefetch = [&](int stage, int kc) {
        uint32_t sb = uS + stage * GSTAGE;
#pragma unroll
        for (int g = 0; g < 4; ++g) {
            int flat = g * 256 + t;
            int row = flat >> 3, grp = flat & 7;
            uint32_t dst = (uint32_t)(row * LDP * 2 + grp * 16);
            cp16(sb + dst, A + (size_t)(m0 + row) * Dn + kc + grp * 8);
            cp16(sb + TILE_B + dst, B + (size_t)(n0 + row) * Dn + kc + grp * 8);
        }
    };

    prefetch(0, 0);
    CP_COMMIT();

    const int NKT = Dn / KC;   // 16
    for (int kt = 0; kt < NKT; ++kt) {
        CP_WAIT0();
        __syncthreads();
        if (kt + 1 < NKT) {
            prefetch((kt + 1) & 1, (kt + 1) * KC);
            CP_COMMIT();
        }

        const uint32_t sb = uS + (kt & 1) * GSTAGE;
        const uint32_t uA = sb, uB = sb + TILE_B;

#pragma unroll
        for (int ks = 0; ks < KC / 16; ++ks) {
            uint32_t ah[2][4];
#pragma unroll
            for (int mf = 0; mf < 2; ++mf) {
                uint32_t ao = aOff + (uint32_t)(mf * 16 * LDP * 2 + ks * 32);
                ldsm_x4(ah[mf][0], ah[mf][1], ah[mf][2], ah[mf][3], uA + ao);
            }
#pragma unroll
            for (int nfp = 0; nfp < 4; ++nfp) {
                uint32_t bo = (uint32_t)(((wc * 64 + nfp * 16 + (lane & 7) +
                                           ((lane & 16) ? 8 : 0)) * LDP +
                                          ks * 16 + ((lane & 8) ? 8 : 0)) * 2);
                uint32_t br[4];
                ldsm_x4(br[0], br[1], br[2], br[3], uB + bo);
#pragma unroll
                for (int mf = 0; mf < 2; ++mf) {
                    mma_f16(acc[mf][2 * nfp], ah[mf], br);
                    mma_f16(acc[mf][2 * nfp + 1], ah[mf], br + 2);
                }
            }
        }
    }

    const int r0 = lane >> 2;
    const int cp = (lane & 3) * 2;
#pragma unroll
    for (int mf = 0; mf < 2; ++mf) {
#pragma unroll
        for (int nf = 0; nf < 8; ++nf) {
            int n1 = n0 + wc * 64 + nf * 8 + cp;
            int hh = n1 >> 6, hd = n1 & 63;
            float b0 = bias[n1], b1 = bias[n1 + 1];
#pragma unroll
            for (int half = 0; half < 2; ++half) {
                int m1 = m0 + wr * 32 + mf * 16 + r0 + half * 8;
                int bb = m1 >> 11, ss = m1 & (Sn - 1);
                float v0 = acc[mf][nf][half * 2 + 0] + b0;
                float v1 = acc[mf][nf][half * 2 + 1] + b1;
                size_t idx = (((size_t)(bb * Hn + hh) * Sn) + ss) * HDn + hd;
                *(__half2*)(outp + idx) = __floats2half2_rn(v0, v1);
            }
        }
    }
}

// ---------------------------------------------------------------------------
// Attention tile: fp16 HMMA, fixed-max softmax, register-resident P.
// ---------------------------------------------------------------------------
#define BQ 64
#define BK 128
#define LDK 72

#define KVST 36864
#define OKH 0
#define OVH 18432
#define OFF_QH 73728
#define OFF_CX 82944
#define OFF_F  99328
#define ATTN_SMEM (OFF_F + 384 * 4)   // 100864

__device__ __forceinline__ void do_attn(char* smem, int t, int b, int h, int q0,
                                        const float* mask, float* out_ctx,
                                        float* out_scores, int write_scores)
{
    const uint32_t uS = smem_u32(smem);
    const uint32_t uQh = uS + OFF_QH;
    float* CX = (float*)(smem + OFF_CX);
    float* fs = (float*)(smem + OFF_F);
    float* PSm = fs;         // [2][64]
    float* MK = fs + 128;    // [2][128]

    const int lane = t & 31;
    const int wid = t >> 5;
    const int wm = wid & 3;
    const int wn = wid >> 2;
    const int r0 = lane >> 2;
    const int cp = (lane & 3) * 2;

    const size_t bh = (size_t)(b * Hn + h);
    const size_t base = bh * Sn;
    const float* mrow = mask + (size_t)b * Sn;

    auto prefetch = [&](int stage, int k0) {
        uint32_t sb = uS + stage * KVST;
#pragma unroll
        for (int g = 0; g < 4; ++g) {
            int flat = g * 256 + t;
            int row = flat >> 3, grp = flat & 7;
            uint32_t dst = (uint32_t)(row * LDK * 2 + grp * 16);
            size_t src = (base + k0 + row) * HDn + grp * 8;
            cp16(sb + OKH + dst, g_kh + src);
            cp16(sb + OVH + dst, g_vh + src);
        }
        if (t < BK) MK[stage * 128 + t] = mrow[k0 + t];
    };

#pragma unroll
    for (int g = 0; g < 2; ++g) {
        int flat = g * 256 + t;
        int row = flat >> 3, grp = flat & 7;
        uint32_t dst = (uint32_t)(row * LDK * 2 + grp * 16);
        *(uint4*)(smem + OFF_QH + dst) =
            *(const uint4*)(g_qh + (base + q0 + row) * HDn + grp * 8);
    }
    prefetch(0, 0);
    CP_COMMIT();
    __syncthreads();

    uint32_t qf[4][4];
    {
        uint32_t ao = (uint32_t)(((wm * 16 + (lane & 15)) * LDK + (lane >> 4) * 8) * 2);
#pragma unroll
        for (int ks = 0; ks < 4; ++ks)
            ldsm_x4(qf[ks][0], qf[ks][1], qf[ks][2], qf[ks][3], uQh + ao + ks * 32);
    }

    float cacc[8][4];
#pragma unroll
    for (int i = 0; i < 8; ++i)
#pragma unroll
        for (int e = 0; e < 4; ++e) cacc[i][e] = 0.f;

    float rsum0 = 0.f, rsum1 = 0.f;
    const float scale = 0.125f;

    const int NT = Sn / BK;   // 16
    for (int kt = 0; kt < NT; ++kt) {
        const int k0 = kt * BK;
        const int stage = kt & 1;
        CP_WAIT0();
        __syncthreads();
        if (kt + 1 < NT) {
            prefetch(stage ^ 1, k0 + BK);
            CP_COMMIT();
        }

        const uint32_t uKh = uS + stage * KVST + OKH;
        const uint32_t uVh = uS + stage * KVST + OVH;
        const float* MKs = MK + stage * 128;

        float sacc[8][4];
#pragma unroll
        for (int nf = 0; nf < 8; ++nf)
#pragma unroll
            for (int e = 0; e < 4; ++e) sacc[nf][e] = 0.f;

#pragma unroll
        for (int ks = 0; ks < 4; ++ks) {
#pragma unroll
            for (int nfp = 0; nfp < 4; ++nfp) {
                uint32_t bo = (uint32_t)(((wn * 64 + nfp * 16 + (lane & 7) +
                                           ((lane & 16) ? 8 : 0)) * LDK +
                                          ks * 16 + ((lane & 8) ? 8 : 0)) * 2);
                uint32_t br[4];
                ldsm_x4(br[0], br[1], br[2], br[3], uKh + bo);
                mma_f16(sacc[2 * nfp], qf[ks], br);
                mma_f16(sacc[2 * nfp + 1], qf[ks], br + 2);
            }
        }

        uint32_t pA[4][4];
        size_t rbase = (bh * Sn + (size_t)(q0 + wm * 16 + r0)) * Sn + k0 + wn * 64 + cp;
#pragma unroll
        for (int ksl = 0; ksl < 4; ++ksl) {
            float pv[2][4];
#pragma unroll
            for (int j = 0; j < 2; ++j) {
                int nf = 2 * ksl + j;
                int col = wn * 64 + nf * 8 + cp;
                float m0v = MKs[col], m1v = MKs[col + 1];
                float s0 = sacc[nf][0] * scale + m0v;
                float s1 = sacc[nf][1] * scale + m1v;
                float s2 = sacc[nf][2] * scale + m0v;
                float s3 = sacc[nf][3] * scale + m1v;
                if (write_scores) {
                    stcs2(out_scores + rbase + nf * 8, make_float2(s0, s1));
                    stcs2(out_scores + rbase + 8 * (size_t)Sn + nf * 8, make_float2(s2, s3));
                }
                pv[j][0] = __expf(s0);
                pv[j][1] = __expf(s1);
                pv[j][2] = __expf(s2);
                pv[j][3] = __expf(s3);
                rsum0 += pv[j][0] + pv[j][1];
                rsum1 += pv[j][2] + pv[j][3];
            }
            pA[ksl][0] = pf2(pv[0][0], pv[0][1]);
            pA[ksl][1] = pf2(pv[0][2], pv[0][3]);
            pA[ksl][2] = pf2(pv[1][0], pv[1][1]);
            pA[ksl][3] = pf2(pv[1][2], pv[1][3]);
        }

#pragma unroll
        for (int ksl = 0; ksl < 4; ++ksl) {
#pragma unroll
            for (int dfp = 0; dfp < 4; ++dfp) {
                uint32_t bo = (uint32_t)(((wn * 64 + ksl * 16 + (lane & 7) +
                                           ((lane & 8) ? 8 : 0)) * LDK +
                                          dfp * 16 + ((lane & 16) ? 8 : 0)) * 2);
                uint32_t vf[4];
                ldsm_x4t(vf[0], vf[1], vf[2], vf[3], uVh + bo);
                mma_f16(cacc[2 * dfp], pA[ksl], vf);
                mma_f16(cacc[2 * dfp + 1], pA[ksl], vf + 2);
            }
        }
    }

    rsum0 += __shfl_xor_sync(0xffffffffu, rsum0, 1);
    rsum0 += __shfl_xor_sync(0xffffffffu, rsum0, 2);
    rsum1 += __shfl_xor_sync(0xffffffffu, rsum1, 1);
    rsum1 += __shfl_xor_sync(0xffffffffu, rsum1, 2);
    if ((lane & 3) == 0) {
        PSm[wn * 64 + wm * 16 + r0] = rsum0;
        PSm[wn * 64 + wm * 16 + r0 + 8] = rsum1;
    }
    if (wn == 1) {
        float* dst = CX + (wm * 32 + lane) * 32;
#pragma unroll
        for (int df = 0; df < 8; ++df) {
            dst[df * 4 + 0] = cacc[df][0];
            dst[df * 4 + 1] = cacc[df][1];
            dst[df * 4 + 2] = cacc[df][2];
            dst[df * 4 + 3] = cacc[df][3];
        }
    }
    __syncthreads();
    if (wn == 0) {
        const float* srcp = CX + (wm * 32 + lane) * 32;
        float inv0 = 1.f / (PSm[wm * 16 + r0] + PSm[64 + wm * 16 + r0]);
        float inv1 = 1.f / (PSm[wm * 16 + r0 + 8] + PSm[64 + wm * 16 + r0 + 8]);
        size_t row = (size_t)b * Sn + q0 + wm * 16 + r0;
#pragma unroll
        for (int df = 0; df < 8; ++df) {
            int gd = h * HDn + df * 8 + cp;
            float c0 = (cacc[df][0] + srcp[df * 4 + 0]) * inv0;
            float c1 = (cacc[df][1] + srcp[df * 4 + 1]) * inv0;
            float c2 = (cacc[df][2] + srcp[df * 4 + 2]) * inv1;
            float c3 = (cacc[df][3] + srcp[df * 4 + 3]) * inv1;
            *(float2*)(out_ctx + row * Dn + gd) = make_float2(c0, c1);
            *(float2*)(out_ctx + (row + 8) * Dn + gd) = make_float2(c2, c3);
        }
    }
}

// ---------------------------------------------------------------------------
// Single fused persistent work-queue kernel.
//   items [0,24):    W conversion  (which order K,V,Q x 8 n-blocks)
//   items [24,120):  X conversion  (K 32, V 32, Q 32 m-blocks)
//   items [120,888): gemm tiles grouped by (b, nblk): 16 K, 16 V, 16 Q
//   items [888,1912): attn tiles in matching group order
// Queue order == dependency order -> dynamic stealing is deadlock-free.
// Last finishing CTA re-zeroes all sync state for the next graph replay.
// ---------------------------------------------------------------------------
#define NCV 120
#define NG 888
#define NTOT 1912
#define FUSED_GRID 304

__global__ __launch_bounds__(256, 2) void fused_kernel(
    const float* __restrict__ qx, const float* __restrict__ kx, const float* __restrict__ vx,
    const float* __restrict__ Wq, const float* __restrict__ Wk, const float* __restrict__ Wv,
    const float* __restrict__ bq, const float* __restrict__ bk, const float* __restrict__ bv,
    const float* __restrict__ mask,
    float* __restrict__ out_ctx,
    float* __restrict__ out_scores,
    int write_scores)
{
    extern __shared__ char smem[];
    __shared__ int s_item;
    const int t = threadIdx.x;
    static const int worder[3] = {1, 2, 0};   // conversion which-order K,V,Q

    for (;;) {
        __syncthreads();                       // prior item fully done with smem
        if (t == 0) s_item = atomicAdd(&g_wq, 1);
        __syncthreads();
        const int it = s_item;
        if (it >= NTOT) break;

        if (it < 24) {
            // ---- W conversion: one 128-row n-block ----
            const int which = worder[it >> 3];
            const int nblk = it & 7;
            const float* src = which == 0 ? Wq : (which == 1 ? Wk : Wv);
            do_convert(t, src, g_wh + (size_t)which * WSZ, nblk);
            __threadfence();
            __syncthreads();
            if (t == 0) atomicExch(&g_wcv[which * 8 + nblk], 1);
        } else if (it < NCV) {
            // ---- X conversion: one 128-row m-block ----
            const int xi = it - 24;
            const int which = worder[xi >> 5];
            const int mblk = xi & 31;
            const float* src = which == 0 ? qx : (which == 1 ? kx : vx);
            do_convert(t, src, g_xh + (size_t)which * XSZ, mblk);
            __threadfence();
            __syncthreads();
            if (t == 0) atomicExch(&g_xcv[which * 32 + mblk], 1);
        } else if (it < NG) {
            // ---- gemm tile ----
            const int gi = it - NCV;
            const int grp = gi / 48, r = gi % 48;
            const int b = grp >> 3, nblk = grp & 7;
            const int which = (r < 16) ? 1 : (r < 32 ? 2 : 0);
            const int mblk = b * 16 + (r & 15);
            const float* bias = which == 0 ? bq : (which == 1 ? bk : bv);

            wait_ge(&g_xcv[which * 32 + mblk], 1);
            wait_ge(&g_wcv[which * 8 + nblk], 1);

            do_gemm(smem, t, which, mblk * 128, nblk * 128, bias);

            __threadfence();
            __syncthreads();
            if (t == 0) {
                if (which == 0) atomicExch(&g_qd[mblk * 8 + nblk], 1);
                else            atomicAdd(&g_kv[(which - 1) * 16 + b * 8 + nblk], 1);
            }
        } else {
            // ---- attention tile ----
            const int a = it - NG;
            const int grp = a >> 6, r = a & 63;
            const int b = grp >> 3, nblk = grp & 7;
            const int h = nblk * 2 + (r >> 5);
            const int q0 = (r & 31) * 64;

            wait_ge(&g_kv[b * 8 + nblk], 16);
            wait_ge(&g_kv[16 + b * 8 + nblk], 16);
            wait_ge(&g_qd[(b * 16 + (q0 >> 7)) * 8 + nblk], 1);

            do_attn(smem, t, b, h, q0, mask, out_ctx, out_scores, write_scores);
        }
    }

    // Last finishing CTA resets all sync state for the next replay.
    __syncthreads();
    if (t == 0) {
        if (atomicAdd(&g_done, 1) == FUSED_GRID - 1) {
            g_wq = 0;
            for (int i = 0; i < 32; ++i) g_kv[i] = 0;
            for (int i = 0; i < 256; ++i) g_qd[i] = 0;
            for (int i = 0; i < 96; ++i) g_xcv[i] = 0;
            for (int i = 0; i < 24; ++i) g_wcv[i] = 0;
            __threadfence();
            g_done = 0;
        }
    }
}

extern "C" void kernel_launch(void* const* d_in, const int* in_sizes, int n_in,
                              void* d_out, int out_size)
{
    const float* q    = (const float*)d_in[0];
    const float* k    = (const float*)d_in[1];
    const float* v    = (const float*)d_in[2];
    const float* mask = (const float*)d_in[3];
    const float* Wq   = (const float*)d_in[4];
    const float* bq   = (const float*)d_in[5];
    const float* Wk   = (const float*)d_in[6];
    const float* bk   = (const float*)d_in[7];
    const float* Wv   = (const float*)d_in[8];
    const float* bv   = (const float*)d_in[9];
    float* out = (float*)d_out;

    const long long CTX = (long long)Bn * Sn * Dn;
    const long long SC  = (long long)Bn * Hn * Sn * (long long)Sn;

    int ws = 0;
    float* sc_out = out;
    if ((long long)out_size >= CTX + SC) { sc_out = out + CTX; ws = 1; }

    cudaFuncSetAttribute(fused_kernel,
                         cudaFuncAttributeMaxDynamicSharedMemorySize, ATTN_SMEM);
    fused_kernel<<<FUSED_GRID, 256, ATTN_SMEM>>>(
        q, k, v, Wq, Wk, Wv, bq, bk, bv, mask, out, sc_out, ws);
}

// round 14
// speedup vs baseline: 1.0254x; 1.0254x over previous
#include <cuda_runtime.h>
#include <cuda_fp16.h>
#include <math.h>
#include <stdint.h>

#define Bn 2
#define Sn 2048
#define Dn 1024
#define Hn 16
#define HDn 64

#define XSZ (Bn * Sn * Dn)
#define WSZ (Dn * Dn)

// Projected tensors, fp16, layout [B,H,S,HD].
__device__ __half g_qh[XSZ];
__device__ __half g_kh[XSZ];
__device__ __half g_vh[XSZ];

// fp16 gemm inputs.
__device__ __half g_xh[3 * XSZ];
__device__ __half g_wh[3 * WSZ];

// Sync state (zero-initialized at load; last CTA re-zeroes at kernel end).
__device__ int g_wq;         // work counter
__device__ int g_done;       // finished-CTA counter
__device__ int g_kv[32];     // [which-1][b][nblk] completed m-blocks (target 16)
__device__ int g_qd[256];    // [mblk][nblk] Q tile done flags
__device__ int g_xcv[96];    // [which][mblk] X conversion chunks done (target 4)
__device__ int g_wcv[24];    // [which][nblk] W conversion chunks done (target 4)

// ---------------------------------------------------------------------------
// Helpers.
// ---------------------------------------------------------------------------
__device__ __forceinline__ uint32_t smem_u32(const void* p) {
    uint32_t a;
    asm("{ .reg .u64 t; cvta.to.shared.u64 t, %1; cvt.u32.u64 %0, t; }"
        : "=r"(a) : "l"(p));
    return a;
}
__device__ __forceinline__ void ldsm_x4(uint32_t& r0, uint32_t& r1,
                                        uint32_t& r2, uint32_t& r3, uint32_t a) {
    asm volatile("ldmatrix.sync.aligned.m8n8.x4.shared.b16 {%0,%1,%2,%3}, [%4];"
                 : "=r"(r0), "=r"(r1), "=r"(r2), "=r"(r3) : "r"(a));
}
__device__ __forceinline__ void ldsm_x4t(uint32_t& r0, uint32_t& r1,
                                         uint32_t& r2, uint32_t& r3, uint32_t a) {
    asm volatile("ldmatrix.sync.aligned.m8n8.x4.trans.shared.b16 {%0,%1,%2,%3}, [%4];"
                 : "=r"(r0), "=r"(r1), "=r"(r2), "=r"(r3) : "r"(a));
}
__device__ __forceinline__ void mma_f16(float* c, const uint32_t* a,
                                        const uint32_t* b) {
    asm volatile(
        "mma.sync.aligned.m16n8k16.row.col.f32.f16.f16.f32 "
        "{%0,%1,%2,%3}, {%4,%5,%6,%7}, {%8,%9}, {%0,%1,%2,%3};"
        : "+f"(c[0]), "+f"(c[1]), "+f"(c[2]), "+f"(c[3])
        : "r"(a[0]), "r"(a[1]), "r"(a[2]), "r"(a[3]), "r"(b[0]), "r"(b[1]));
}
__device__ __forceinline__ void cp16(uint32_t dst, const void* src) {
    asm volatile("cp.async.cg.shared.global [%0], [%1], 16;"
                 :: "r"(dst), "l"(src));
}
#define CP_COMMIT() asm volatile("cp.async.commit_group;" ::: "memory")
#define CP_WAIT0()  asm volatile("cp.async.wait_group 0;" ::: "memory")
__device__ __forceinline__ void stcs2(float* p, float2 v) {
    asm volatile("st.global.cs.v2.f32 [%0], {%1, %2};" :: "l"(p), "f"(v.x), "f"(v.y));
}
__device__ __forceinline__ uint32_t pf2(float lo, float hi) {
    uint32_t r;
    asm("cvt.rn.f16x2.f32 %0, %1, %2;" : "=r"(r) : "f"(hi), "f"(lo));
    return r;
}
__device__ __forceinline__ int ldacq(const int* p) {
    int v;
    asm volatile("ld.acquire.gpu.global.b32 %0, [%1];" : "=r"(v) : "l"(p));
    return v;
}
__device__ __forceinline__ void wait_ge(const int* p, int v) {
    while (ldacq(p) < v) __nanosleep(200);
}

// ---------------------------------------------------------------------------
// Conversion item: one 32-row chunk (32*1024 floats) fp32 -> fp16.
// ---------------------------------------------------------------------------
__device__ __forceinline__ void do_convert(int t, const float* __restrict__ src,
                                           __half* __restrict__ dst, int chunk)
{
    const size_t base4 = (size_t)chunk * 8192;   // float4 index of chunk start
#pragma unroll 4
    for (int i = t; i < 8192; i += 256) {
        float4 x = ((const float4*)src)[base4 + i];
        ((__half2*)dst)[(base4 + i) * 2 + 0] = __floats2half2_rn(x.x, x.y);
        ((__half2*)dst)[(base4 + i) * 2 + 1] = __floats2half2_rn(x.z, x.w);
    }
}

// ---------------------------------------------------------------------------
// GEMM tile (single-term fp16 HMMA), 128x128, K-chunk 64, 2-stage ring.
// ---------------------------------------------------------------------------
#define KC 64
#define LDP 72
#define TILE_B (128 * LDP * 2)     // 18432
#define GSTAGE (2 * TILE_B)        // 36864

__device__ __forceinline__ void do_gemm(char* smem, int t, int which,
                                        int m0, int n0, const float* bias)
{
    const uint32_t uS = smem_u32(smem);
    const int wid = t >> 5;
    const int lane = t & 31;
    const int wr = wid & 3;
    const int wc = wid >> 2;

    const __half* A = g_xh + (size_t)which * XSZ;
    const __half* B = g_wh + (size_t)which * WSZ;
    __half* outp = which == 0 ? g_qh : (which == 1 ? g_kh : g_vh);

    float acc[2][8][4];
#pragma unroll
    for (int i = 0; i < 2; ++i)
#pragma unroll
        for (int j = 0; j < 8; ++j)
#pragma unroll
            for (int e = 0; e < 4; ++e) acc[i][j][e] = 0.f;

    const uint32_t aOff = (uint32_t)(((wr * 32 + (lane & 15)) * LDP + (lane >> 4) * 8) * 2);

    auto prefetch = [&](int stage, int kc) {
        uint32_t sb = uS + stage * GSTAGE;
#pragma unroll
        for (int g = 0; g < 4; ++g) {
            int flat = g * 256 + t;
            int row = flat >> 3, grp = flat & 7;
            uint32_t dst = (uint32_t)(row * LDP * 2 + grp * 16);
            cp16(sb + dst, A + (size_t)(m0 + row) * Dn + kc + grp * 8);
            cp16(sb + TILE_B + dst, B + (size_t)(n0 + row) * Dn + kc + grp * 8);
        }
    };

    prefetch(0, 0);
    CP_COMMIT();

    const int NKT = Dn / KC;   // 16
    for (int kt = 0; kt < NKT; ++kt) {
        CP_WAIT0();
        __syncthreads();
        if (kt + 1 < NKT) {
            prefetch((kt + 1) & 1, (kt + 1) * KC);
            CP_COMMIT();
        }

        const uint32_t sb = uS + (kt & 1) * GSTAGE;
        const uint32_t uA = sb, uB = sb + TILE_B;

#pragma unroll
        for (int ks = 0; ks < KC / 16; ++ks) {
            uint32_t ah[2][4];
#pragma unroll
            for (int mf = 0; mf < 2; ++mf) {
                uint32_t ao = aOff + (uint32_t)(mf * 16 * LDP * 2 + ks * 32);
                ldsm_x4(ah[mf][0], ah[mf][1], ah[mf][2], ah[mf][3], uA + ao);
            }
#pragma unroll
            for (int nfp = 0; nfp < 4; ++nfp) {
                uint32_t bo = (uint32_t)(((wc * 64 + nfp * 16 + (lane & 7) +
                                           ((lane & 16) ? 8 : 0)) * LDP +
                                          ks * 16 + ((lane & 8) ? 8 : 0)) * 2);
                uint32_t br[4];
                ldsm_x4(br[0], br[1], br[2], br[3], uB + bo);
#pragma unroll
                for (int mf = 0; mf < 2; ++mf) {
                    mma_f16(acc[mf][2 * nfp], ah[mf], br);
                    mma_f16(acc[mf][2 * nfp + 1], ah[mf], br + 2);
                }
            }
        }
    }

    const int r0 = lane >> 2;
    const int cp = (lane & 3) * 2;
#pragma unroll
    for (int mf = 0; mf < 2; ++mf) {
#pragma unroll
        for (int nf = 0; nf < 8; ++nf) {
            int n1 = n0 + wc * 64 + nf * 8 + cp;
            int hh = n1 >> 6, hd = n1 & 63;
            float b0 = bias[n1], b1 = bias[n1 + 1];
#pragma unroll
            for (int half = 0; half < 2; ++half) {
                int m1 = m0 + wr * 32 + mf * 16 + r0 + half * 8;
                int bb = m1 >> 11, ss = m1 & (Sn - 1);
                float v0 = acc[mf][nf][half * 2 + 0] + b0;
                float v1 = acc[mf][nf][half * 2 + 1] + b1;
                size_t idx = (((size_t)(bb * Hn + hh) * Sn) + ss) * HDn + hd;
                *(__half2*)(outp + idx) = __floats2half2_rn(v0, v1);
            }
        }
    }
}

// ---------------------------------------------------------------------------
// Attention tile: fp16 HMMA, fixed-max softmax, register-resident P.
// ---------------------------------------------------------------------------
#define BQ 64
#define BK 128
#define LDK 72

#define KVST 36864
#define OKH 0
#define OVH 18432
#define OFF_QH 73728
#define OFF_CX 82944
#define OFF_F  99328
#define ATTN_SMEM (OFF_F + 384 * 4)   // 100864

__device__ __forceinline__ void do_attn(char* smem, int t, int b, int h, int q0,
                                        const float* mask, float* out_ctx,
                                        float* out_scores, int write_scores)
{
    const uint32_t uS = smem_u32(smem);
    const uint32_t uQh = uS + OFF_QH;
    float* CX = (float*)(smem + OFF_CX);
    float* fs = (float*)(smem + OFF_F);
    float* PSm = fs;         // [2][64]
    float* MK = fs + 128;    // [2][128]

    const int lane = t & 31;
    const int wid = t >> 5;
    const int wm = wid & 3;
    const int wn = wid >> 2;
    const int r0 = lane >> 2;
    const int cp = (lane & 3) * 2;

    const size_t bh = (size_t)(b * Hn + h);
    const size_t base = bh * Sn;
    const float* mrow = mask + (size_t)b * Sn;

    auto prefetch = [&](int stage, int k0) {
        uint32_t sb = uS + stage * KVST;
#pragma unroll
        for (int g = 0; g < 4; ++g) {
            int flat = g * 256 + t;
            int row = flat >> 3, grp = flat & 7;
            uint32_t dst = (uint32_t)(row * LDK * 2 + grp * 16);
            size_t src = (base + k0 + row) * HDn + grp * 8;
            cp16(sb + OKH + dst, g_kh + src);
            cp16(sb + OVH + dst, g_vh + src);
        }
        if (t < BK) MK[stage * 128 + t] = mrow[k0 + t];
    };

#pragma unroll
    for (int g = 0; g < 2; ++g) {
        int flat = g * 256 + t;
        int row = flat >> 3, grp = flat & 7;
        uint32_t dst = (uint32_t)(row * LDK * 2 + grp * 16);
        *(uint4*)(smem + OFF_QH + dst) =
            *(const uint4*)(g_qh + (base + q0 + row) * HDn + grp * 8);
    }
    prefetch(0, 0);
    CP_COMMIT();
    __syncthreads();

    uint32_t qf[4][4];
    {
        uint32_t ao = (uint32_t)(((wm * 16 + (lane & 15)) * LDK + (lane >> 4) * 8) * 2);
#pragma unroll
        for (int ks = 0; ks < 4; ++ks)
            ldsm_x4(qf[ks][0], qf[ks][1], qf[ks][2], qf[ks][3], uQh + ao + ks * 32);
    }

    float cacc[8][4];
#pragma unroll
    for (int i = 0; i < 8; ++i)
#pragma unroll
        for (int e = 0; e < 4; ++e) cacc[i][e] = 0.f;

    float rsum0 = 0.f, rsum1 = 0.f;
    const float scale = 0.125f;

    const int NT = Sn / BK;   // 16
    for (int kt = 0; kt < NT; ++kt) {
        const int k0 = kt * BK;
        const int stage = kt & 1;
        CP_WAIT0();
        __syncthreads();
        if (kt + 1 < NT) {
            prefetch(stage ^ 1, k0 + BK);
            CP_COMMIT();
        }

        const uint32_t uKh = uS + stage * KVST + OKH;
        const uint32_t uVh = uS + stage * KVST + OVH;
        const float* MKs = MK + stage * 128;

        float sacc[8][4];
#pragma unroll
        for (int nf = 0; nf < 8; ++nf)
#pragma unroll
            for (int e = 0; e < 4; ++e) sacc[nf][e] = 0.f;

#pragma unroll
        for (int ks = 0; ks < 4; ++ks) {
#pragma unroll
            for (int nfp = 0; nfp < 4; ++nfp) {
                uint32_t bo = (uint32_t)(((wn * 64 + nfp * 16 + (lane & 7) +
                                           ((lane & 16) ? 8 : 0)) * LDK +
                                          ks * 16 + ((lane & 8) ? 8 : 0)) * 2);
                uint32_t br[4];
                ldsm_x4(br[0], br[1], br[2], br[3], uKh + bo);
                mma_f16(sacc[2 * nfp], qf[ks], br);
                mma_f16(sacc[2 * nfp + 1], qf[ks], br + 2);
            }
        }

        uint32_t pA[4][4];
        size_t rbase = (bh * Sn + (size_t)(q0 + wm * 16 + r0)) * Sn + k0 + wn * 64 + cp;
#pragma unroll
        for (int ksl = 0; ksl < 4; ++ksl) {
            float pv[2][4];
#pragma unroll
            for (int j = 0; j < 2; ++j) {
                int nf = 2 * ksl + j;
                int col = wn * 64 + nf * 8 + cp;
                float m0v = MKs[col], m1v = MKs[col + 1];
                float s0 = sacc[nf][0] * scale + m0v;
                float s1 = sacc[nf][1] * scale + m1v;
                float s2 = sacc[nf][2] * scale + m0v;
                float s3 = sacc[nf][3] * scale + m1v;
                if (write_scores) {
                    stcs2(out_scores + rbase + nf * 8, make_float2(s0, s1));
                    stcs2(out_scores + rbase + 8 * (size_t)Sn + nf * 8, make_float2(s2, s3));
                }
                pv[j][0] = __expf(s0);
                pv[j][1] = __expf(s1);
                pv[j][2] = __expf(s2);
                pv[j][3] = __expf(s3);
                rsum0 += pv[j][0] + pv[j][1];
                rsum1 += pv[j][2] + pv[j][3];
            }
            pA[ksl][0] = pf2(pv[0][0], pv[0][1]);
            pA[ksl][1] = pf2(pv[0][2], pv[0][3]);
            pA[ksl][2] = pf2(pv[1][0], pv[1][1]);
            pA[ksl][3] = pf2(pv[1][2], pv[1][3]);
        }

#pragma unroll
        for (int ksl = 0; ksl < 4; ++ksl) {
#pragma unroll
            for (int dfp = 0; dfp < 4; ++dfp) {
                uint32_t bo = (uint32_t)(((wn * 64 + ksl * 16 + (lane & 7) +
                                           ((lane & 8) ? 8 : 0)) * LDK +
                                          dfp * 16 + ((lane & 16) ? 8 : 0)) * 2);
                uint32_t vf[4];
                ldsm_x4t(vf[0], vf[1], vf[2], vf[3], uVh + bo);
                mma_f16(cacc[2 * dfp], pA[ksl], vf);
                mma_f16(cacc[2 * dfp + 1], pA[ksl], vf + 2);
            }
        }
    }

    rsum0 += __shfl_xor_sync(0xffffffffu, rsum0, 1);
    rsum0 += __shfl_xor_sync(0xffffffffu, rsum0, 2);
    rsum1 += __shfl_xor_sync(0xffffffffu, rsum1, 1);
    rsum1 += __shfl_xor_sync(0xffffffffu, rsum1, 2);
    if ((lane & 3) == 0) {
        PSm[wn * 64 + wm * 16 + r0] = rsum0;
        PSm[wn * 64 + wm * 16 + r0 + 8] = rsum1;
    }
    if (wn == 1) {
        float* dst = CX + (wm * 32 + lane) * 32;
#pragma unroll
        for (int df = 0; df < 8; ++df) {
            dst[df * 4 + 0] = cacc[df][0];
            dst[df * 4 + 1] = cacc[df][1];
            dst[df * 4 + 2] = cacc[df][2];
            dst[df * 4 + 3] = cacc[df][3];
        }
    }
    __syncthreads();
    if (wn == 0) {
        const float* srcp = CX + (wm * 32 + lane) * 32;
        float inv0 = 1.f / (PSm[wm * 16 + r0] + PSm[64 + wm * 16 + r0]);
        float inv1 = 1.f / (PSm[wm * 16 + r0 + 8] + PSm[64 + wm * 16 + r0 + 8]);
        size_t row = (size_t)b * Sn + q0 + wm * 16 + r0;
#pragma unroll
        for (int df = 0; df < 8; ++df) {
            int gd = h * HDn + df * 8 + cp;
            float c0 = (cacc[df][0] + srcp[df * 4 + 0]) * inv0;
            float c1 = (cacc[df][1] + srcp[df * 4 + 1]) * inv0;
            float c2 = (cacc[df][2] + srcp[df * 4 + 2]) * inv1;
            float c3 = (cacc[df][3] + srcp[df * 4 + 3]) * inv1;
            *(float2*)(out_ctx + row * Dn + gd) = make_float2(c0, c1);
            *(float2*)(out_ctx + (row + 8) * Dn + gd) = make_float2(c2, c3);
        }
    }
}

// ---------------------------------------------------------------------------
// Single fused persistent work-queue kernel.
//   items [0,96):     W conversion, 32-row chunks (K,V,Q x 32 chunks)
//   items [96,480):   X conversion, 32-row chunks (K,V,Q x 128 chunks)
//   items [480,1248): gemm tiles grouped by (b, nblk): 16 K, 16 V, 16 Q
//   items [1248,2272): attn tiles in matching group order
// Queue order == dependency order -> dynamic stealing is deadlock-free.
// 480 conversion items > grid size, so the whole machine converts in the
// prologue (no spin-starvation). Last CTA re-zeroes sync state for replay.
// ---------------------------------------------------------------------------
#define NWCV 96
#define NCV 480
#define NG 1248
#define NTOT 2272
#define FUSED_GRID 304

__global__ __launch_bounds__(256, 2) void fused_kernel(
    const float* __restrict__ qx, const float* __restrict__ kx, const float* __restrict__ vx,
    const float* __restrict__ Wq, const float* __restrict__ Wk, const float* __restrict__ Wv,
    const float* __restrict__ bq, const float* __restrict__ bk, const float* __restrict__ bv,
    const float* __restrict__ mask,
    float* __restrict__ out_ctx,
    float* __restrict__ out_scores,
    int write_scores)
{
    extern __shared__ char smem[];
    __shared__ int s_item;
    const int t = threadIdx.x;
    static const int worder[3] = {1, 2, 0};   // conversion which-order K,V,Q

    for (;;) {
        __syncthreads();                       // prior item fully done with smem
        if (t == 0) s_item = atomicAdd(&g_wq, 1);
        __syncthreads();
        const int it = s_item;
        if (it >= NTOT) break;

        if (it < NWCV) {
            // ---- W conversion: one 32-row chunk ----
            const int which = worder[it >> 5];
            const int chunk = it & 31;
            const float* src = which == 0 ? Wq : (which == 1 ? Wk : Wv);
            do_convert(t, src, g_wh + (size_t)which * WSZ, chunk);
            __threadfence();
            __syncthreads();
            if (t == 0) atomicAdd(&g_wcv[which * 8 + (chunk >> 2)], 1);
        } else if (it < NCV) {
            // ---- X conversion: one 32-row chunk ----
            const int xi = it - NWCV;
            const int which = worder[xi >> 7];
            const int chunk = xi & 127;
            const float* src = which == 0 ? qx : (which == 1 ? kx : vx);
            do_convert(t, src, g_xh + (size_t)which * XSZ, chunk);
            __threadfence();
            __syncthreads();
            if (t == 0) atomicAdd(&g_xcv[which * 32 + (chunk >> 2)], 1);
        } else if (it < NG) {
            // ---- gemm tile ----
            const int gi = it - NCV;
            const int grp = gi / 48, r = gi % 48;
            const int b = grp >> 3, nblk = grp & 7;
            const int which = (r < 16) ? 1 : (r < 32 ? 2 : 0);
            const int mblk = b * 16 + (r & 15);
            const float* bias = which == 0 ? bq : (which == 1 ? bk : bv);

            wait_ge(&g_xcv[which * 32 + mblk], 4);
            wait_ge(&g_wcv[which * 8 + nblk], 4);

            do_gemm(smem, t, which, mblk * 128, nblk * 128, bias);

            __threadfence();
            __syncthreads();
            if (t == 0) {
                if (which == 0) atomicExch(&g_qd[mblk * 8 + nblk], 1);
                else            atomicAdd(&g_kv[(which - 1) * 16 + b * 8 + nblk], 1);
            }
        } else {
            // ---- attention tile ----
            const int a = it - NG;
            const int grp = a >> 6, r = a & 63;
            const int b = grp >> 3, nblk = grp & 7;
            const int h = nblk * 2 + (r >> 5);
            const int q0 = (r & 31) * 64;

            wait_ge(&g_kv[b * 8 + nblk], 16);
            wait_ge(&g_kv[16 + b * 8 + nblk], 16);
            wait_ge(&g_qd[(b * 16 + (q0 >> 7)) * 8 + nblk], 1);

            do_attn(smem, t, b, h, q0, mask, out_ctx, out_scores, write_scores);
        }
    }

    // Last finishing CTA resets all sync state for the next replay.
    __syncthreads();
    if (t == 0) {
        if (atomicAdd(&g_done, 1) == FUSED_GRID - 1) {
            g_wq = 0;
            for (int i = 0; i < 32; ++i) g_kv[i] = 0;
            for (int i = 0; i < 256; ++i) g_qd[i] = 0;
            for (int i = 0; i < 96; ++i) g_xcv[i] = 0;
            for (int i = 0; i < 24; ++i) g_wcv[i] = 0;
            __threadfence();
            g_done = 0;
        }
    }
}

extern "C" void kernel_launch(void* const* d_in, const int* in_sizes, int n_in,
                              void* d_out, int out_size)
{
    const float* q    = (const float*)d_in[0];
    const float* k    = (const float*)d_in[1];
    const float* v    = (const float*)d_in[2];
    const float* mask = (const float*)d_in[3];
    const float* Wq   = (const float*)d_in[4];
    const float* bq   = (const float*)d_in[5];
    const float* Wk   = (const float*)d_in[6];
    const float* bk   = (const float*)d_in[7];
    const float* Wv   = (const float*)d_in[8];
    const float* bv   = (const float*)d_in[9];
    float* out = (float*)d_out;

    const long long CTX = (long long)Bn * Sn * Dn;
    const long long SC  = (long long)Bn * Hn * Sn * (long long)Sn;

    int ws = 0;
    float* sc_out = out;
    if ((long long)out_size >= CTX + SC) { sc_out = out + CTX; ws = 1; }

    cudaFuncSetAttribute(fused_kernel,
                         cudaFuncAttributeMaxDynamicSharedMemorySize, ATTN_SMEM);
    fused_kernel<<<FUSED_GRID, 256, ATTN_SMEM>>>(
        q, k, v, Wq, Wk, Wv, bq, bk, bv, mask, out, sc_out, ws);
}

// round 15
// speedup vs baseline: 1.0565x; 1.0304x over previous
#include <cuda_runtime.h>
#include <cuda_fp16.h>
#include <math.h>
#include <stdint.h>

#define Bn 2
#define Sn 2048
#define Dn 1024
#define Hn 16
#define HDn 64

#define XSZ (Bn * Sn * Dn)
#define WSZ (Dn * Dn)

// Projected tensors, fp16, layout [B,H,S,HD].
__device__ __half g_qh[XSZ];
__device__ __half g_kh[XSZ];
__device__ __half g_vh[XSZ];

// fp16 gemm inputs.
__device__ __half g_xh[3 * XSZ];
__device__ __half g_wh[3 * WSZ];

// Sync state for the fused work-queue kernel (zeroed inside split_f16 each
// launch; stream order guarantees it's clean before fused_kernel starts).
__device__ int g_wq;        // work counter
__device__ int g_kv[32];    // [which-1][b][nblk] completed m-blocks (target 16)
__device__ int g_qd[256];   // [mblk][nblk] Q tile done flags

// ---------------------------------------------------------------------------
// Helpers.
// ---------------------------------------------------------------------------
__device__ __forceinline__ uint32_t smem_u32(const void* p) {
    uint32_t a;
    asm("{ .reg .u64 t; cvta.to.shared.u64 t, %1; cvt.u32.u64 %0, t; }"
        : "=r"(a) : "l"(p));
    return a;
}
__device__ __forceinline__ void ldsm_x4(uint32_t& r0, uint32_t& r1,
                                        uint32_t& r2, uint32_t& r3, uint32_t a) {
    asm volatile("ldmatrix.sync.aligned.m8n8.x4.shared.b16 {%0,%1,%2,%3}, [%4];"
                 : "=r"(r0), "=r"(r1), "=r"(r2), "=r"(r3) : "r"(a));
}
__device__ __forceinline__ void ldsm_x4t(uint32_t& r0, uint32_t& r1,
                                         uint32_t& r2, uint32_t& r3, uint32_t a) {
    asm volatile("ldmatrix.sync.aligned.m8n8.x4.trans.shared.b16 {%0,%1,%2,%3}, [%4];"
                 : "=r"(r0), "=r"(r1), "=r"(r2), "=r"(r3) : "r"(a));
}
__device__ __forceinline__ void mma_f16(float* c, const uint32_t* a,
                                        const uint32_t* b) {
    asm volatile(
        "mma.sync.aligned.m16n8k16.row.col.f32.f16.f16.f32 "
        "{%0,%1,%2,%3}, {%4,%5,%6,%7}, {%8,%9}, {%0,%1,%2,%3};"
        : "+f"(c[0]), "+f"(c[1]), "+f"(c[2]), "+f"(c[3])
        : "r"(a[0]), "r"(a[1]), "r"(a[2]), "r"(a[3]), "r"(b[0]), "r"(b[1]));
}
__device__ __forceinline__ void cp16(uint32_t dst, const void* src) {
    asm volatile("cp.async.cg.shared.global [%0], [%1], 16;"
                 :: "r"(dst), "l"(src));
}
#define CP_COMMIT() asm volatile("cp.async.commit_group;" ::: "memory")
#define CP_WAIT0()  asm volatile("cp.async.wait_group 0;" ::: "memory")
__device__ __forceinline__ void stcs2(float* p, float2 v) {
    asm volatile("st.global.cs.v2.f32 [%0], {%1, %2};" :: "l"(p), "f"(v.x), "f"(v.y));
}
__device__ __forceinline__ uint32_t pf2(float lo, float hi) {
    uint32_t r;
    asm("cvt.rn.f16x2.f32 %0, %1, %2;" : "=r"(r) : "f"(hi), "f"(lo));
    return r;
}
__device__ __forceinline__ int ldacq(const int* p) {
    int v;
    asm volatile("ld.acquire.gpu.global.b32 %0, [%1];" : "=r"(v) : "l"(p));
    return v;
}
__device__ __forceinline__ void wait_ge(const int* p, int v) {
    while (ldacq(p) < v) __nanosleep(200);
}

// ---------------------------------------------------------------------------
// fp16 conversion of gemm inputs. z: 0..2 = q,k,v ; 3..5 = Wq,Wk,Wv.
// Block (0, z=0) additionally zeroes the fused-kernel sync state.
// ---------------------------------------------------------------------------
__global__ __launch_bounds__(256) void split_f16(
    const float* __restrict__ q, const float* __restrict__ k, const float* __restrict__ v,
    const float* __restrict__ wq, const float* __restrict__ wk, const float* __restrict__ wv)
{
    const int which = blockIdx.z;
    if (which == 0 && blockIdx.x == 0) {
        int i = threadIdx.x;
        if (i == 0) g_wq = 0;
        if (i < 32) g_kv[i] = 0;
        g_qd[i] = 0;                       // 256 threads cover all flags
    }
    const float* src;
    __half* dst;
    int n;
    if (which < 3) {
        src = which == 0 ? q : (which == 1 ? k : v);
        dst = g_xh + (size_t)which * XSZ;
        n = XSZ;
    } else {
        int w = which - 3;
        src = w == 0 ? wq : (w == 1 ? wk : wv);
        dst = g_wh + (size_t)w * WSZ;
        n = WSZ;
    }
    int i4 = blockIdx.x * 256 + threadIdx.x;
    if (i4 * 4 >= n) return;
    float4 x = ((const float4*)src)[i4];
    ((__half2*)dst)[i4 * 2 + 0] = __floats2half2_rn(x.x, x.y);
    ((__half2*)dst)[i4 * 2 + 1] = __floats2half2_rn(x.z, x.w);
}

// ---------------------------------------------------------------------------
// GEMM tile (single-term fp16 HMMA), 128x128, K-chunk 64, 2-stage ring.
// ---------------------------------------------------------------------------
#define KC 64
#define LDP 72
#define TILE_B (128 * LDP * 2)     // 18432
#define GSTAGE (2 * TILE_B)        // 36864

__device__ __forceinline__ void do_gemm(char* smem, int t, int which,
                                        int m0, int n0, const float* bias)
{
    const uint32_t uS = smem_u32(smem);
    const int wid = t >> 5;
    const int lane = t & 31;
    const int wr = wid & 3;
    const int wc = wid >> 2;

    const __half* A = g_xh + (size_t)which * XSZ;
    const __half* B = g_wh + (size_t)which * WSZ;
    __half* outp = which == 0 ? g_qh : (which == 1 ? g_kh : g_vh);

    float acc[2][8][4];
#pragma unroll
    for (int i = 0; i < 2; ++i)
#pragma unroll
        for (int j = 0; j < 8; ++j)
#pragma unroll
            for (int e = 0; e < 4; ++e) acc[i][j][e] = 0.f;

    const uint32_t aOff = (uint32_t)(((wr * 32 + (lane & 15)) * LDP + (lane >> 4) * 8) * 2);

    auto prefetch = [&](int stage, int kc) {
        uint32_t sb = uS + stage * GSTAGE;
#pragma unroll
        for (int g = 0; g < 4; ++g) {
            int flat = g * 256 + t;
            int row = flat >> 3, grp = flat & 7;
            uint32_t dst = (uint32_t)(row * LDP * 2 + grp * 16);
            cp16(sb + dst, A + (size_t)(m0 + row) * Dn + kc + grp * 8);
            cp16(sb + TILE_B + dst, B + (size_t)(n0 + row) * Dn + kc + grp * 8);
        }
    };

    prefetch(0, 0);
    CP_COMMIT();

    const int NKT = Dn / KC;   // 16
    for (int kt = 0; kt < NKT; ++kt) {
        CP_WAIT0();
        __syncthreads();
        if (kt + 1 < NKT) {
            prefetch((kt + 1) & 1, (kt + 1) * KC);
            CP_COMMIT();
        }

        const uint32_t sb = uS + (kt & 1) * GSTAGE;
        const uint32_t uA = sb, uB = sb + TILE_B;

#pragma unroll
        for (int ks = 0; ks < KC / 16; ++ks) {
            uint32_t ah[2][4];
#pragma unroll
            for (int mf = 0; mf < 2; ++mf) {
                uint32_t ao = aOff + (uint32_t)(mf * 16 * LDP * 2 + ks * 32);
                ldsm_x4(ah[mf][0], ah[mf][1], ah[mf][2], ah[mf][3], uA + ao);
            }
#pragma unroll
            for (int nfp = 0; nfp < 4; ++nfp) {
                uint32_t bo = (uint32_t)(((wc * 64 + nfp * 16 + (lane & 7) +
                                           ((lane & 16) ? 8 : 0)) * LDP +
                                          ks * 16 + ((lane & 8) ? 8 : 0)) * 2);
                uint32_t br[4];
                ldsm_x4(br[0], br[1], br[2], br[3], uB + bo);
#pragma unroll
                for (int mf = 0; mf < 2; ++mf) {
                    mma_f16(acc[mf][2 * nfp], ah[mf], br);
                    mma_f16(acc[mf][2 * nfp + 1], ah[mf], br + 2);
                }
            }
        }
    }

    const int r0 = lane >> 2;
    const int cp = (lane & 3) * 2;
#pragma unroll
    for (int mf = 0; mf < 2; ++mf) {
#pragma unroll
        for (int nf = 0; nf < 8; ++nf) {
            int n1 = n0 + wc * 64 + nf * 8 + cp;
            int hh = n1 >> 6, hd = n1 & 63;
            float b0 = bias[n1], b1 = bias[n1 + 1];
#pragma unroll
            for (int half = 0; half < 2; ++half) {
                int m1 = m0 + wr * 32 + mf * 16 + r0 + half * 8;
                int bb = m1 >> 11, ss = m1 & (Sn - 1);
                float v0 = acc[mf][nf][half * 2 + 0] + b0;
                float v1 = acc[mf][nf][half * 2 + 1] + b1;
                size_t idx = (((size_t)(bb * Hn + hh) * Sn) + ss) * HDn + hd;
                *(__half2*)(outp + idx) = __floats2half2_rn(v0, v1);
            }
        }
    }
}

// ---------------------------------------------------------------------------
// Attention tile: fp16 HMMA, fixed-max softmax, register-resident P.
// ---------------------------------------------------------------------------
#define BQ 64
#define BK 128
#define LDK 72

#define KVST 36864
#define OKH 0
#define OVH 18432
#define OFF_QH 73728
#define OFF_CX 82944
#define OFF_F  99328
#define ATTN_SMEM (OFF_F + 384 * 4)   // 100864

__device__ __forceinline__ void do_attn(char* smem, int t, int b, int h, int q0,
                                        const float* mask, float* out_ctx,
                                        float* out_scores, int write_scores)
{
    const uint32_t uS = smem_u32(smem);
    const uint32_t uQh = uS + OFF_QH;
    float* CX = (float*)(smem + OFF_CX);
    float* fs = (float*)(smem + OFF_F);
    float* PSm = fs;         // [2][64]
    float* MK = fs + 128;    // [2][128]

    const int lane = t & 31;
    const int wid = t >> 5;
    const int wm = wid & 3;
    const int wn = wid >> 2;
    const int r0 = lane >> 2;
    const int cp = (lane & 3) * 2;

    const size_t bh = (size_t)(b * Hn + h);
    const size_t base = bh * Sn;
    const float* mrow = mask + (size_t)b * Sn;

    auto prefetch = [&](int stage, int k0) {
        uint32_t sb = uS + stage * KVST;
#pragma unroll
        for (int g = 0; g < 4; ++g) {
            int flat = g * 256 + t;
            int row = flat >> 3, grp = flat & 7;
            uint32_t dst = (uint32_t)(row * LDK * 2 + grp * 16);
            size_t src = (base + k0 + row) * HDn + grp * 8;
            cp16(sb + OKH + dst, g_kh + src);
            cp16(sb + OVH + dst, g_vh + src);
        }
        if (t < BK) MK[stage * 128 + t] = mrow[k0 + t];
    };

#pragma unroll
    for (int g = 0; g < 2; ++g) {
        int flat = g * 256 + t;
        int row = flat >> 3, grp = flat & 7;
        uint32_t dst = (uint32_t)(row * LDK * 2 + grp * 16);
        *(uint4*)(smem + OFF_QH + dst) =
            *(const uint4*)(g_qh + (base + q0 + row) * HDn + grp * 8);
    }
    prefetch(0, 0);
    CP_COMMIT();
    __syncthreads();

    uint32_t qf[4][4];
    {
        uint32_t ao = (uint32_t)(((wm * 16 + (lane & 15)) * LDK + (lane >> 4) * 8) * 2);
#pragma unroll
        for (int ks = 0; ks < 4; ++ks)
            ldsm_x4(qf[ks][0], qf[ks][1], qf[ks][2], qf[ks][3], uQh + ao + ks * 32);
    }

    float cacc[8][4];
#pragma unroll
    for (int i = 0; i < 8; ++i)
#pragma unroll
        for (int e = 0; e < 4; ++e) cacc[i][e] = 0.f;

    float rsum0 = 0.f, rsum1 = 0.f;
    const float scale = 0.125f;

    const int NT = Sn / BK;   // 16
    for (int kt = 0; kt < NT; ++kt) {
        const int k0 = kt * BK;
        const int stage = kt & 1;
        CP_WAIT0();
        __syncthreads();
        if (kt + 1 < NT) {
            prefetch(stage ^ 1, k0 + BK);
            CP_COMMIT();
        }

        const uint32_t uKh = uS + stage * KVST + OKH;
        const uint32_t uVh = uS + stage * KVST + OVH;
        const float* MKs = MK + stage * 128;

        float sacc[8][4];
#pragma unroll
        for (int nf = 0; nf < 8; ++nf)
#pragma unroll
            for (int e = 0; e < 4; ++e) sacc[nf][e] = 0.f;

#pragma unroll
        for (int ks = 0; ks < 4; ++ks) {
#pragma unroll
            for (int nfp = 0; nfp < 4; ++nfp) {
                uint32_t bo = (uint32_t)(((wn * 64 + nfp * 16 + (lane & 7) +
                                           ((lane & 16) ? 8 : 0)) * LDK +
                                          ks * 16 + ((lane & 8) ? 8 : 0)) * 2);
                uint32_t br[4];
                ldsm_x4(br[0], br[1], br[2], br[3], uKh + bo);
                mma_f16(sacc[2 * nfp], qf[ks], br);
                mma_f16(sacc[2 * nfp + 1], qf[ks], br + 2);
            }
        }

        uint32_t pA[4][4];
        size_t rbase = (bh * Sn + (size_t)(q0 + wm * 16 + r0)) * Sn + k0 + wn * 64 + cp;
#pragma unroll
        for (int ksl = 0; ksl < 4; ++ksl) {
            float pv[2][4];
#pragma unroll
            for (int j = 0; j < 2; ++j) {
                int nf = 2 * ksl + j;
                int col = wn * 64 + nf * 8 + cp;
                float m0v = MKs[col], m1v = MKs[col + 1];
                float s0 = sacc[nf][0] * scale + m0v;
                float s1 = sacc[nf][1] * scale + m1v;
                float s2 = sacc[nf][2] * scale + m0v;
                float s3 = sacc[nf][3] * scale + m1v;
                if (write_scores) {
                    stcs2(out_scores + rbase + nf * 8, make_float2(s0, s1));
                    stcs2(out_scores + rbase + 8 * (size_t)Sn + nf * 8, make_float2(s2, s3));
                }
                pv[j][0] = __expf(s0);
                pv[j][1] = __expf(s1);
                pv[j][2] = __expf(s2);
                pv[j][3] = __expf(s3);
                rsum0 += pv[j][0] + pv[j][1];
                rsum1 += pv[j][2] + pv[j][3];
            }
            pA[ksl][0] = pf2(pv[0][0], pv[0][1]);
            pA[ksl][1] = pf2(pv[0][2], pv[0][3]);
            pA[ksl][2] = pf2(pv[1][0], pv[1][1]);
            pA[ksl][3] = pf2(pv[1][2], pv[1][3]);
        }

#pragma unroll
        for (int ksl = 0; ksl < 4; ++ksl) {
#pragma unroll
            for (int dfp = 0; dfp < 4; ++dfp) {
                uint32_t bo = (uint32_t)(((wn * 64 + ksl * 16 + (lane & 7) +
                                           ((lane & 8) ? 8 : 0)) * LDK +
                                          dfp * 16 + ((lane & 16) ? 8 : 0)) * 2);
                uint32_t vf[4];
                ldsm_x4t(vf[0], vf[1], vf[2], vf[3], uVh + bo);
                mma_f16(cacc[2 * dfp], pA[ksl], vf);
                mma_f16(cacc[2 * dfp + 1], pA[ksl], vf + 2);
            }
        }
    }

    rsum0 += __shfl_xor_sync(0xffffffffu, rsum0, 1);
    rsum0 += __shfl_xor_sync(0xffffffffu, rsum0, 2);
    rsum1 += __shfl_xor_sync(0xffffffffu, rsum1, 1);
    rsum1 += __shfl_xor_sync(0xffffffffu, rsum1, 2);
    if ((lane & 3) == 0) {
        PSm[wn * 64 + wm * 16 + r0] = rsum0;
        PSm[wn * 64 + wm * 16 + r0 + 8] = rsum1;
    }
    if (wn == 1) {
        float* dst = CX + (wm * 32 + lane) * 32;
#pragma unroll
        for (int df = 0; df < 8; ++df) {
            dst[df * 4 + 0] = cacc[df][0];
            dst[df * 4 + 1] = cacc[df][1];
            dst[df * 4 + 2] = cacc[df][2];
            dst[df * 4 + 3] = cacc[df][3];
        }
    }
    __syncthreads();
    if (wn == 0) {
        const float* srcp = CX + (wm * 32 + lane) * 32;
        float inv0 = 1.f / (PSm[wm * 16 + r0] + PSm[64 + wm * 16 + r0]);
        float inv1 = 1.f / (PSm[wm * 16 + r0 + 8] + PSm[64 + wm * 16 + r0 + 8]);
        size_t row = (size_t)b * Sn + q0 + wm * 16 + r0;
#pragma unroll
        for (int df = 0; df < 8; ++df) {
            int gd = h * HDn + df * 8 + cp;
            float c0 = (cacc[df][0] + srcp[df * 4 + 0]) * inv0;
            float c1 = (cacc[df][1] + srcp[df * 4 + 1]) * inv0;
            float c2 = (cacc[df][2] + srcp[df * 4 + 2]) * inv1;
            float c3 = (cacc[df][3] + srcp[df * 4 + 3]) * inv1;
            *(float2*)(out_ctx + row * Dn + gd) = make_float2(c0, c1);
            *(float2*)(out_ctx + (row + 8) * Dn + gd) = make_float2(c2, c3);
        }
    }
}

// ---------------------------------------------------------------------------
// Fused persistent work-queue kernel (round-12 proven structure).
// Items [0,768): gemm tiles grouped by (b, nblk): 16 K, 16 V, 16 Q.
// Items [768,1792): attn tiles in matching group order.
// Queue order == dependency order -> dynamic stealing is deadlock-free.
// ---------------------------------------------------------------------------
#define NG 768
#define NTOT 1792
#define FUSED_GRID 296

__global__ __launch_bounds__(256, 2) void fused_kernel(
    const float* __restrict__ bq, const float* __restrict__ bk, const float* __restrict__ bv,
    const float* __restrict__ mask,
    float* __restrict__ out_ctx,
    float* __restrict__ out_scores,
    int write_scores)
{
    extern __shared__ char smem[];
    __shared__ int s_item;
    const int t = threadIdx.x;

    for (;;) {
        __syncthreads();                       // prior item fully done with smem
        if (t == 0) s_item = atomicAdd(&g_wq, 1);
        __syncthreads();
        const int it = s_item;
        if (it >= NTOT) break;

        if (it < NG) {
            // ---- gemm tile ----
            const int grp = it / 48, r = it % 48;
            const int b = grp >> 3, nblk = grp & 7;
            const int which = (r < 16) ? 1 : (r < 32 ? 2 : 0);
            const int mblk = b * 16 + (r & 15);
            const float* bias = which == 0 ? bq : (which == 1 ? bk : bv);

            do_gemm(smem, t, which, mblk * 128, nblk * 128, bias);

            __threadfence();
            __syncthreads();
            if (t == 0) {
                if (which == 0) atomicExch(&g_qd[mblk * 8 + nblk], 1);
                else            atomicAdd(&g_kv[(which - 1) * 16 + b * 8 + nblk], 1);
            }
        } else {
            // ---- attention tile ----
            const int a = it - NG;
            const int grp = a >> 6, r = a & 63;
            const int b = grp >> 3, nblk = grp & 7;
            const int h = nblk * 2 + (r >> 5);
            const int q0 = (r & 31) * 64;

            wait_ge(&g_kv[b * 8 + nblk], 16);
            wait_ge(&g_kv[16 + b * 8 + nblk], 16);
            wait_ge(&g_qd[(b * 16 + (q0 >> 7)) * 8 + nblk], 1);

            do_attn(smem, t, b, h, q0, mask, out_ctx, out_scores, write_scores);
        }
    }
}

extern "C" void kernel_launch(void* const* d_in, const int* in_sizes, int n_in,
                              void* d_out, int out_size)
{
    const float* q    = (const float*)d_in[0];
    const float* k    = (const float*)d_in[1];
    const float* v    = (const float*)d_in[2];
    const float* mask = (const float*)d_in[3];
    const float* Wq   = (const float*)d_in[4];
    const float* bq   = (const float*)d_in[5];
    const float* Wk   = (const float*)d_in[6];
    const float* bk   = (const float*)d_in[7];
    const float* Wv   = (const float*)d_in[8];
    const float* bv   = (const float*)d_in[9];
    float* out = (float*)d_out;

    const long long CTX = (long long)Bn * Sn * Dn;
    const long long SC  = (long long)Bn * Hn * Sn * (long long)Sn;

    int ws = 0;
    float* sc_out = out;
    if ((long long)out_size >= CTX + SC) { sc_out = out + CTX; ws = 1; }

    split_f16<<<dim3(XSZ / (256 * 4), 1, 6), 256>>>(q, k, v, Wq, Wk, Wv);

    cudaFuncSetAttribute(fused_kernel,
                         cudaFuncAttributeMaxDynamicSharedMemorySize, ATTN_SMEM);
    fused_kernel<<<FUSED_GRID, 256, ATTN_SMEM>>>(bq, bk, bv, mask, out, sc_out, ws);
}

// round 16
// speedup vs baseline: 1.0726x; 1.0152x over previous
#include <cuda_runtime.h>
#include <cuda_fp16.h>
#include <math.h>
#include <stdint.h>

#define Bn 2
#define Sn 2048
#define Dn 1024
#define Hn 16
#define HDn 64

#define XSZ (Bn * Sn * Dn)
#define WSZ (Dn * Dn)

// Projected tensors, fp16, layout [B,H,S,HD].
__device__ __half g_qh[XSZ];
__device__ __half g_kh[XSZ];
__device__ __half g_vh[XSZ];

// fp16 gemm inputs.
__device__ __half g_xh[3 * XSZ];
__device__ __half g_wh[3 * WSZ];

// Sync state for the fused work-queue kernel (zeroed inside split_f16 each
// launch; stream order guarantees it's clean before fused_kernel starts).
__device__ int g_wq;        // work counter
__device__ int g_kv[32];    // [which-1][b][nblk] completed m-blocks (target 16)
__device__ int g_qd[256];   // [mblk][nblk] Q tile done flags

// ---------------------------------------------------------------------------
// Helpers.
// ---------------------------------------------------------------------------
__device__ __forceinline__ uint32_t smem_u32(const void* p) {
    uint32_t a;
    asm("{ .reg .u64 t; cvta.to.shared.u64 t, %1; cvt.u32.u64 %0, t; }"
        : "=r"(a) : "l"(p));
    return a;
}
__device__ __forceinline__ void ldsm_x4(uint32_t& r0, uint32_t& r1,
                                        uint32_t& r2, uint32_t& r3, uint32_t a) {
    asm volatile("ldmatrix.sync.aligned.m8n8.x4.shared.b16 {%0,%1,%2,%3}, [%4];"
                 : "=r"(r0), "=r"(r1), "=r"(r2), "=r"(r3) : "r"(a));
}
__device__ __forceinline__ void ldsm_x4t(uint32_t& r0, uint32_t& r1,
                                         uint32_t& r2, uint32_t& r3, uint32_t a) {
    asm volatile("ldmatrix.sync.aligned.m8n8.x4.trans.shared.b16 {%0,%1,%2,%3}, [%4];"
                 : "=r"(r0), "=r"(r1), "=r"(r2), "=r"(r3) : "r"(a));
}
__device__ __forceinline__ void mma_f16(float* c, const uint32_t* a,
                                        const uint32_t* b) {
    asm volatile(
        "mma.sync.aligned.m16n8k16.row.col.f32.f16.f16.f32 "
        "{%0,%1,%2,%3}, {%4,%5,%6,%7}, {%8,%9}, {%0,%1,%2,%3};"
        : "+f"(c[0]), "+f"(c[1]), "+f"(c[2]), "+f"(c[3])
        : "r"(a[0]), "r"(a[1]), "r"(a[2]), "r"(a[3]), "r"(b[0]), "r"(b[1]));
}
__device__ __forceinline__ void cp16(uint32_t dst, const void* src) {
    asm volatile("cp.async.cg.shared.global [%0], [%1], 16;"
                 :: "r"(dst), "l"(src));
}
#define CP_COMMIT() asm volatile("cp.async.commit_group;" ::: "memory")
#define CP_WAIT0()  asm volatile("cp.async.wait_group 0;" ::: "memory")
__device__ __forceinline__ void stcs2(float* p, float2 v) {
    asm volatile("st.global.cs.v2.f32 [%0], {%1, %2};" :: "l"(p), "f"(v.x), "f"(v.y));
}
// pack two fp32 into f16x2: low half = lo, high half = hi.
__device__ __forceinline__ uint32_t pf2(float lo, float hi) {
    uint32_t r;
    asm("cvt.rn.f16x2.f32 %0, %1, %2;" : "=r"(r) : "f"(hi), "f"(lo));
    return r;
}
// packed fp16x2 2^x
__device__ __forceinline__ uint32_t h2ex2(uint32_t a) {
    uint32_t r;
    asm("ex2.approx.f16x2 %0, %1;" : "=r"(r) : "r"(a));
    return r;
}
__device__ __forceinline__ int ldacq(const int* p) {
    int v;
    asm volatile("ld.acquire.gpu.global.b32 %0, [%1];" : "=r"(v) : "l"(p));
    return v;
}
__device__ __forceinline__ void wait_ge(const int* p, int v) {
    while (ldacq(p) < v) __nanosleep(200);
}

// ---------------------------------------------------------------------------
// fp16 conversion of gemm inputs. z: 0..2 = q,k,v ; 3..5 = Wq,Wk,Wv.
// Block (0, z=0) additionally zeroes the fused-kernel sync state.
// ---------------------------------------------------------------------------
__global__ __launch_bounds__(256) void split_f16(
    const float* __restrict__ q, const float* __restrict__ k, const float* __restrict__ v,
    const float* __restrict__ wq, const float* __restrict__ wk, const float* __restrict__ wv)
{
    const int which = blockIdx.z;
    if (which == 0 && blockIdx.x == 0) {
        int i = threadIdx.x;
        if (i == 0) g_wq = 0;
        if (i < 32) g_kv[i] = 0;
        g_qd[i] = 0;                       // 256 threads cover all flags
    }
    const float* src;
    __half* dst;
    int n;
    if (which < 3) {
        src = which == 0 ? q : (which == 1 ? k : v);
        dst = g_xh + (size_t)which * XSZ;
        n = XSZ;
    } else {
        int w = which - 3;
        src = w == 0 ? wq : (w == 1 ? wk : wv);
        dst = g_wh + (size_t)w * WSZ;
        n = WSZ;
    }
    int i4 = blockIdx.x * 256 + threadIdx.x;
    if (i4 * 4 >= n) return;
    float4 x = ((const float4*)src)[i4];
    ((__half2*)dst)[i4 * 2 + 0] = __floats2half2_rn(x.x, x.y);
    ((__half2*)dst)[i4 * 2 + 1] = __floats2half2_rn(x.z, x.w);
}

// ---------------------------------------------------------------------------
// GEMM tile (single-term fp16 HMMA), 128x128, K-chunk 64, 2-stage ring.
// ---------------------------------------------------------------------------
#define KC 64
#define LDP 72
#define TILE_B (128 * LDP * 2)     // 18432
#define GSTAGE (2 * TILE_B)        // 36864

__device__ __forceinline__ void do_gemm(char* smem, int t, int which,
                                        int m0, int n0, const float* bias)
{
    const uint32_t uS = smem_u32(smem);
    const int wid = t >> 5;
    const int lane = t & 31;
    const int wr = wid & 3;
    const int wc = wid >> 2;

    const __half* A = g_xh + (size_t)which * XSZ;
    const __half* B = g_wh + (size_t)which * WSZ;
    __half* outp = which == 0 ? g_qh : (which == 1 ? g_kh : g_vh);

    float acc[2][8][4];
#pragma unroll
    for (int i = 0; i < 2; ++i)
#pragma unroll
        for (int j = 0; j < 8; ++j)
#pragma unroll
            for (int e = 0; e < 4; ++e) acc[i][j][e] = 0.f;

    const uint32_t aOff = (uint32_t)(((wr * 32 + (lane & 15)) * LDP + (lane >> 4) * 8) * 2);

    auto prefetch = [&](int stage, int kc) {
        uint32_t sb = uS + stage * GSTAGE;
#pragma unroll
        for (int g = 0; g < 4; ++g) {
            int flat = g * 256 + t;
            int row = flat >> 3, grp = flat & 7;
            uint32_t dst = (uint32_t)(row * LDP * 2 + grp * 16);
            cp16(sb + dst, A + (size_t)(m0 + row) * Dn + kc + grp * 8);
            cp16(sb + TILE_B + dst, B + (size_t)(n0 + row) * Dn + kc + grp * 8);
        }
    };

    prefetch(0, 0);
    CP_COMMIT();

    const int NKT = Dn / KC;   // 16
    for (int kt = 0; kt < NKT; ++kt) {
        CP_WAIT0();
        __syncthreads();
        if (kt + 1 < NKT) {
            prefetch((kt + 1) & 1, (kt + 1) * KC);
            CP_COMMIT();
        }

        const uint32_t sb = uS + (kt & 1) * GSTAGE;
        const uint32_t uA = sb, uB = sb + TILE_B;

#pragma unroll
        for (int ks = 0; ks < KC / 16; ++ks) {
            uint32_t ah[2][4];
#pragma unroll
            for (int mf = 0; mf < 2; ++mf) {
                uint32_t ao = aOff + (uint32_t)(mf * 16 * LDP * 2 + ks * 32);
                ldsm_x4(ah[mf][0], ah[mf][1], ah[mf][2], ah[mf][3], uA + ao);
            }
#pragma unroll
            for (int nfp = 0; nfp < 4; ++nfp) {
                uint32_t bo = (uint32_t)(((wc * 64 + nfp * 16 + (lane & 7) +
                                           ((lane & 16) ? 8 : 0)) * LDP +
                                          ks * 16 + ((lane & 8) ? 8 : 0)) * 2);
                uint32_t br[4];
                ldsm_x4(br[0], br[1], br[2], br[3], uB + bo);
#pragma unroll
                for (int mf = 0; mf < 2; ++mf) {
                    mma_f16(acc[mf][2 * nfp], ah[mf], br);
                    mma_f16(acc[mf][2 * nfp + 1], ah[mf], br + 2);
                }
            }
        }
    }

    const int r0 = lane >> 2;
    const int cp = (lane & 3) * 2;
#pragma unroll
    for (int mf = 0; mf < 2; ++mf) {
#pragma unroll
        for (int nf = 0; nf < 8; ++nf) {
            int n1 = n0 + wc * 64 + nf * 8 + cp;
            int hh = n1 >> 6, hd = n1 & 63;
            float b0 = bias[n1], b1 = bias[n1 + 1];
#pragma unroll
            for (int half = 0; half < 2; ++half) {
                int m1 = m0 + wr * 32 + mf * 16 + r0 + half * 8;
                int bb = m1 >> 11, ss = m1 & (Sn - 1);
                float v0 = acc[mf][nf][half * 2 + 0] + b0;
                float v1 = acc[mf][nf][half * 2 + 1] + b1;
                size_t idx = (((size_t)(bb * Hn + hh) * Sn) + ss) * HDn + hd;
                *(__half2*)(outp + idx) = __floats2half2_rn(v0, v1);
            }
        }
    }
}

// ---------------------------------------------------------------------------
// Attention tile: fp16 HMMA, fixed-max softmax, register-resident P.
// exp via ex2.approx.f16x2 directly into PV A-fragments; row sums computed
// by an extra MMA against an all-ones B fragment (consistent with PV).
// ---------------------------------------------------------------------------
#define BQ 64
#define BK 128
#define LDK 72

#define KVST 36864
#define OKH 0
#define OVH 18432
#define OFF_QH 73728
#define OFF_CX 82944
#define OFF_F  99328
#define ATTN_SMEM (OFF_F + 384 * 4)   // 100864

__device__ __forceinline__ void do_attn(char* smem, int t, int b, int h, int q0,
                                        const float* mask, float* out_ctx,
                                        float* out_scores, int write_scores)
{
    const uint32_t uS = smem_u32(smem);
    const uint32_t uQh = uS + OFF_QH;
    float* CX = (float*)(smem + OFF_CX);
    float* fs = (float*)(smem + OFF_F);
    float* PSm = fs;         // [2][64]
    float* MK = fs + 128;    // [2][128]

    const int lane = t & 31;
    const int wid = t >> 5;
    const int wm = wid & 3;
    const int wn = wid >> 2;
    const int r0 = lane >> 2;
    const int cp = (lane & 3) * 2;

    const size_t bh = (size_t)(b * Hn + h);
    const size_t base = bh * Sn;
    const float* mrow = mask + (size_t)b * Sn;

    auto prefetch = [&](int stage, int k0) {
        uint32_t sb = uS + stage * KVST;
#pragma unroll
        for (int g = 0; g < 4; ++g) {
            int flat = g * 256 + t;
            int row = flat >> 3, grp = flat & 7;
            uint32_t dst = (uint32_t)(row * LDK * 2 + grp * 16);
            size_t src = (base + k0 + row) * HDn + grp * 8;
            cp16(sb + OKH + dst, g_kh + src);
            cp16(sb + OVH + dst, g_vh + src);
        }
        if (t < BK) MK[stage * 128 + t] = mrow[k0 + t];
    };

#pragma unroll
    for (int g = 0; g < 2; ++g) {
        int flat = g * 256 + t;
        int row = flat >> 3, grp = flat & 7;
        uint32_t dst = (uint32_t)(row * LDK * 2 + grp * 16);
        *(uint4*)(smem + OFF_QH + dst) =
            *(const uint4*)(g_qh + (base + q0 + row) * HDn + grp * 8);
    }
    prefetch(0, 0);
    CP_COMMIT();
    __syncthreads();

    uint32_t qf[4][4];
    {
        uint32_t ao = (uint32_t)(((wm * 16 + (lane & 15)) * LDK + (lane >> 4) * 8) * 2);
#pragma unroll
        for (int ks = 0; ks < 4; ++ks)
            ldsm_x4(qf[ks][0], qf[ks][1], qf[ks][2], qf[ks][3], uQh + ao + ks * 32);
    }

    float cacc[8][4];
#pragma unroll
    for (int i = 0; i < 8; ++i)
#pragma unroll
        for (int e = 0; e < 4; ++e) cacc[i][e] = 0.f;
    float csum[4] = {0.f, 0.f, 0.f, 0.f};   // row-sum accumulator (ones-MMA)

    const uint32_t ones_frag[2] = {0x3C003C00u, 0x3C003C00u};
    const float scale = 0.125f;
    const float L2E = 1.4426950408889634f;

    const int NT = Sn / BK;   // 16
    for (int kt = 0; kt < NT; ++kt) {
        const int k0 = kt * BK;
        const int stage = kt & 1;
        CP_WAIT0();
        __syncthreads();
        if (kt + 1 < NT) {
            prefetch(stage ^ 1, k0 + BK);
            CP_COMMIT();
        }

        const uint32_t uKh = uS + stage * KVST + OKH;
        const uint32_t uVh = uS + stage * KVST + OVH;
        const float* MKs = MK + stage * 128;

        float sacc[8][4];
#pragma unroll
        for (int nf = 0; nf < 8; ++nf)
#pragma unroll
            for (int e = 0; e < 4; ++e) sacc[nf][e] = 0.f;

#pragma unroll
        for (int ks = 0; ks < 4; ++ks) {
#pragma unroll
            for (int nfp = 0; nfp < 4; ++nfp) {
                uint32_t bo = (uint32_t)(((wn * 64 + nfp * 16 + (lane & 7) +
                                           ((lane & 16) ? 8 : 0)) * LDK +
                                          ks * 16 + ((lane & 8) ? 8 : 0)) * 2);
                uint32_t br[4];
                ldsm_x4(br[0], br[1], br[2], br[3], uKh + bo);
                mma_f16(sacc[2 * nfp], qf[ks], br);
                mma_f16(sacc[2 * nfp + 1], qf[ks], br + 2);
            }
        }

        // scale+mask, stream scores, exp (f16x2) straight into A-fragments,
        // row sums via ones-MMA.
        uint32_t pA[4][4];
        size_t rbase = (bh * Sn + (size_t)(q0 + wm * 16 + r0)) * Sn + k0 + wn * 64 + cp;
#pragma unroll
        for (int ksl = 0; ksl < 4; ++ksl) {
            float s[2][4];
#pragma unroll
            for (int j = 0; j < 2; ++j) {
                int nf = 2 * ksl + j;
                int col = wn * 64 + nf * 8 + cp;
                float m0v = MKs[col], m1v = MKs[col + 1];
                s[j][0] = sacc[nf][0] * scale + m0v;
                s[j][1] = sacc[nf][1] * scale + m1v;
                s[j][2] = sacc[nf][2] * scale + m0v;
                s[j][3] = sacc[nf][3] * scale + m1v;
                if (write_scores) {
                    stcs2(out_scores + rbase + nf * 8, make_float2(s[j][0], s[j][1]));
                    stcs2(out_scores + rbase + 8 * (size_t)Sn + nf * 8,
                          make_float2(s[j][2], s[j][3]));
                }
            }
            pA[ksl][0] = h2ex2(pf2(s[0][0] * L2E, s[0][1] * L2E));
            pA[ksl][1] = h2ex2(pf2(s[0][2] * L2E, s[0][3] * L2E));
            pA[ksl][2] = h2ex2(pf2(s[1][0] * L2E, s[1][1] * L2E));
            pA[ksl][3] = h2ex2(pf2(s[1][2] * L2E, s[1][3] * L2E));
            mma_f16(csum, pA[ksl], ones_frag);
        }

#pragma unroll
        for (int ksl = 0; ksl < 4; ++ksl) {
#pragma unroll
            for (int dfp = 0; dfp < 4; ++dfp) {
                uint32_t bo = (uint32_t)(((wn * 64 + ksl * 16 + (lane & 7) +
                                           ((lane & 8) ? 8 : 0)) * LDK +
                                          dfp * 16 + ((lane & 16) ? 8 : 0)) * 2);
                uint32_t vf[4];
                ldsm_x4t(vf[0], vf[1], vf[2], vf[3], uVh + bo);
                mma_f16(cacc[2 * dfp], pA[ksl], vf);
                mma_f16(cacc[2 * dfp + 1], pA[ksl], vf + 2);
            }
        }
    }

    // Row sums: csum[0] = row r0, csum[2] = row r0+8 (all quad lanes equal).
    if ((lane & 3) == 0) {
        PSm[wn * 64 + wm * 16 + r0] = csum[0];
        PSm[wn * 64 + wm * 16 + r0 + 8] = csum[2];
    }
    if (wn == 1) {
        float* dst = CX + (wm * 32 + lane) * 32;
#pragma unroll
        for (int df = 0; df < 8; ++df) {
            dst[df * 4 + 0] = cacc[df][0];
            dst[df * 4 + 1] = cacc[df][1];
            dst[df * 4 + 2] = cacc[df][2];
            dst[df * 4 + 3] = cacc[df][3];
        }
    }
    __syncthreads();
    if (wn == 0) {
        const float* srcp = CX + (wm * 32 + lane) * 32;
        float inv0 = 1.f / (PSm[wm * 16 + r0] + PSm[64 + wm * 16 + r0]);
        float inv1 = 1.f / (PSm[wm * 16 + r0 + 8] + PSm[64 + wm * 16 + r0 + 8]);
        size_t row = (size_t)b * Sn + q0 + wm * 16 + r0;
#pragma unroll
        for (int df = 0; df < 8; ++df) {
            int gd = h * HDn + df * 8 + cp;
            float c0 = (cacc[df][0] + srcp[df * 4 + 0]) * inv0;
            float c1 = (cacc[df][1] + srcp[df * 4 + 1]) * inv0;
            float c2 = (cacc[df][2] + srcp[df * 4 + 2]) * inv1;
            float c3 = (cacc[df][3] + srcp[df * 4 + 3]) * inv1;
            *(float2*)(out_ctx + row * Dn + gd) = make_float2(c0, c1);
            *(float2*)(out_ctx + (row + 8) * Dn + gd) = make_float2(c2, c3);
        }
    }
}

// ---------------------------------------------------------------------------
// Fused persistent work-queue kernel (round-12 proven structure).
// Items [0,768): gemm tiles grouped by (b, nblk): 16 K, 16 V, 16 Q.
// Items [768,1792): attn tiles in matching group order.
// Queue order == dependency order -> dynamic stealing is deadlock-free.
// ---------------------------------------------------------------------------
#define NG 768
#define NTOT 1792
#define FUSED_GRID 296

__global__ __launch_bounds__(256, 2) void fused_kernel(
    const float* __restrict__ bq, const float* __restrict__ bk, const float* __restrict__ bv,
    const float* __restrict__ mask,
    float* __restrict__ out_ctx,
    float* __restrict__ out_scores,
    int write_scores)
{
    extern __shared__ char smem[];
    __shared__ int s_item;
    const int t = threadIdx.x;

    for (;;) {
        __syncthreads();                       // prior item fully done with smem
        if (t == 0) s_item = atomicAdd(&g_wq, 1);
        __syncthreads();
        const int it = s_item;
        if (it >= NTOT) break;

        if (it < NG) {
            // ---- gemm tile ----
            const int grp = it / 48, r = it % 48;
            const int b = grp >> 3, nblk = grp & 7;
            const int which = (r < 16) ? 1 : (r < 32 ? 2 : 0);
            const int mblk = b * 16 + (r & 15);
            const float* bias = which == 0 ? bq : (which == 1 ? bk : bv);

            do_gemm(smem, t, which, mblk * 128, nblk * 128, bias);

            __threadfence();
            __syncthreads();
            if (t == 0) {
                if (which == 0) atomicExch(&g_qd[mblk * 8 + nblk], 1);
                else            atomicAdd(&g_kv[(which - 1) * 16 + b * 8 + nblk], 1);
            }
        } else {
            // ---- attention tile ----
            const int a = it - NG;
            const int grp = a >> 6, r = a & 63;
            const int b = grp >> 3, nblk = grp & 7;
            const int h = nblk * 2 + (r >> 5);
            const int q0 = (r & 31) * 64;

            wait_ge(&g_kv[b * 8 + nblk], 16);
            wait_ge(&g_kv[16 + b * 8 + nblk], 16);
            wait_ge(&g_qd[(b * 16 + (q0 >> 7)) * 8 + nblk], 1);

            do_attn(smem, t, b, h, q0, mask, out_ctx, out_scores, write_scores);
        }
    }
}

extern "C" void kernel_launch(void* const* d_in, const int* in_sizes, int n_in,
                              void* d_out, int out_size)
{
    const float* q    = (const float*)d_in[0];
    const float* k    = (const float*)d_in[1];
    const float* v    = (const float*)d_in[2];
    const float* mask = (const float*)d_in[3];
    const float* Wq   = (const float*)d_in[4];
    const float* bq   = (const float*)d_in[5];
    const float* Wk   = (const float*)d_in[6];
    const float* bk   = (const float*)d_in[7];
    const float* Wv   = (const float*)d_in[8];
    const float* bv   = (const float*)d_in[9];
    float* out = (float*)d_out;

    const long long CTX = (long long)Bn * Sn * Dn;
    const long long SC  = (long long)Bn * Hn * Sn * (long long)Sn;

    int ws = 0;
    float* sc_out = out;
    if ((long long)out_size >= CTX + SC) { sc_out = out + CTX; ws = 1; }

    split_f16<<<dim3(XSZ / (256 * 4), 1, 6), 256>>>(q, k, v, Wq, Wk, Wv);

    cudaFuncSetAttribute(fused_kernel,
                         cudaFuncAttributeMaxDynamicSharedMemorySize, ATTN_SMEM);
    fused_kernel<<<FUSED_GRID, 256, ATTN_SMEM>>>(bq, bk, bv, mask, out, sc_out, ws);
}